// round 16
// baseline (speedup 1.0000x reference)
#include <cuda_runtime.h>
#include <cuda_fp16.h>
#include <math.h>
#include <stdint.h>

// Problem constants
#define BATCH 8
#define CIN   192
#define HIMG  128
#define WIMG  128
#define HW    16384           // 128*128
#define MTOT  131072          // BATCH*HW
#define NQKV  576             // 3*C
#define NH    6
#define HD    32
#define WS    8
#define NWIN  64              // WS*WS
#define SCALE 0.17677669529663687f   // 32^-0.5

// ---------------- scratch (device globals; no runtime allocation) -----------
__device__ __align__(16) unsigned short d_xh [(size_t)MTOT * CIN];   // x^T fp16 [m][c]
__device__ __align__(16) unsigned short d_qkv[(size_t)MTOT * NQKV];  // fp16 [m][576]
__device__ __align__(16) unsigned short d_yb [(size_t)MTOT * CIN];   // fp16 [m][192]
__device__ __align__(16) unsigned short d_wfh[NQKV * CIN];           // fp16 [576][192]
__device__ __align__(16) unsigned short d_pwh[CIN * CIN];            // fp16 [192][192]
__device__ float d_bfused[NQKV];
__device__ float d_biasT[NH * NWIN * NWIN];      // [head][n][m]

// ---------------- helpers ----------------------------------------------------
__device__ __forceinline__ void mma_f16(float c[4], const uint32_t a[4], const uint32_t b[2]) {
    asm volatile(
        "mma.sync.aligned.m16n8k16.row.col.f32.f16.f16.f32 "
        "{%0,%1,%2,%3}, {%4,%5,%6,%7}, {%8,%9}, {%0,%1,%2,%3};"
        : "+f"(c[0]), "+f"(c[1]), "+f"(c[2]), "+f"(c[3])
        : "r"(a[0]), "r"(a[1]), "r"(a[2]), "r"(a[3]), "r"(b[0]), "r"(b[1]));
}
__device__ __forceinline__ uint32_t pack2(float a, float b) {
    __half2 h = __floats2half2_rn(a, b);
    return *reinterpret_cast<uint32_t*>(&h);
}
__device__ __forceinline__ void fma2(unsigned long long& acc, unsigned long long a,
                                     unsigned long long b) {
    asm("fma.rn.f32x2 %0, %1, %2, %0;" : "+l"(acc) : "l"(a), "l"(b));
}
__device__ __forceinline__ void cp16(uint32_t saddr, const void* g) {
    asm volatile("cp.async.cg.shared.global [%0], [%1], 16;" :: "r"(saddr), "l"(g));
}
#define CP_COMMIT() asm volatile("cp.async.commit_group;")
#define CP_WAIT1()  asm volatile("cp.async.wait_group 1;")

#define LDSM4(r, addr) \
    asm volatile("ldmatrix.sync.aligned.m8n8.x4.shared.b16 {%0,%1,%2,%3}, [%4];" \
                 : "=r"((r)[0]), "=r"((r)[1]), "=r"((r)[2]), "=r"((r)[3]) : "r"(addr))
#define LDSM2(r0, r1, addr) \
    asm volatile("ldmatrix.sync.aligned.m8n8.x2.shared.b16 {%0,%1}, [%2];" \
                 : "=r"(r0), "=r"(r1) : "r"(addr))

// ---------------- kernel 1: weight prep (fuse + fp16 convert) ---------------
__global__ void prep_w(const float* __restrict__ QK_w, const float* __restrict__ QK_b,
                       const float* __restrict__ V_w,  const float* __restrict__ V_b,
                       const float* __restrict__ pw) {
    int idx = blockIdx.x * 256 + threadIdx.x;
    if (idx < NQKV * CIN) {
        int n = idx / CIN, k = idx - n * CIN;
        float v = (n < 2 * CIN) ? QK_w[n * CIN + k] : V_w[(n - 2 * CIN) * CIN + k];
        d_wfh[idx] = __half_as_ushort(__float2half(v));
    }
    if (idx < CIN * CIN)
        d_pwh[idx] = __half_as_ushort(__float2half(pw[idx]));
    if (idx < NQKV)
        d_bfused[idx] = (idx < 2 * CIN) ? QK_b[idx] : V_b[idx - 2 * CIN];
}

// ---------------- kernel 2: relative-position bias via meta MLP -------------
__global__ void bias_kernel(const float* __restrict__ w1, const float* __restrict__ b1,
                            const float* __restrict__ w2, const float* __restrict__ b2) {
    int idx = blockIdx.x * 256 + threadIdx.x;   // 0..4095
    if (idx >= NWIN * NWIN) return;
    int n1 = idx >> 6, n2 = idx & 63;
    float di = (float)((n1 >> 3) - (n2 >> 3));
    float dj = (float)((n1 & 7) - (n2 & 7));
    float s0 = (di > 0.f) ? 1.f : ((di < 0.f) ? -1.f : 0.f);
    float s1 = (dj > 0.f) ? 1.f : ((dj < 0.f) ? -1.f : 0.f);
    float rp0 = s0 * log1pf(fabsf(di));
    float rp1 = s1 * log1pf(fabsf(dj));
    float acc[NH];
#pragma unroll
    for (int c = 0; c < NH; c++) acc[c] = b2[c];
    for (int t = 0; t < 256; t++) {
        float h = rp0 * w1[t] + rp1 * w1[256 + t] + b1[t];
        h = fmaxf(h, 0.f);
#pragma unroll
        for (int c = 0; c < NH; c++) acc[c] += h * w2[t * NH + c];
    }
#pragma unroll
    for (int c = 0; c < NH; c++)
        d_biasT[(c * NWIN + n1) * NWIN + n2] = acc[c];
}

// ---------------- kernel 3: transpose+convert x -> d_xh fp16 [m][c] ---------
__global__ void __launch_bounds__(256) transpose_x(const float* __restrict__ x) {
    __shared__ float tile[32][33];
    int cb = blockIdx.x << 5;
    int mb = blockIdx.y << 5;
    int b  = mb >> 14;
    int hw0 = mb & (HW - 1);
    int tx = threadIdx.x & 31, ty = threadIdx.x >> 5;
    const float* src = x + (size_t)b * CIN * HW + hw0;
#pragma unroll
    for (int i = 0; i < 4; i++)
        tile[ty + i * 8][tx] = src[(size_t)(cb + ty + i * 8) * HW + tx];
    __syncthreads();
#pragma unroll
    for (int i = 0; i < 4; i++) {
        int m = mb + ty + i * 8;
        d_xh[(size_t)m * CIN + cb + tx] =
            __half_as_ushort(__float2half(tile[tx][ty + i * 8]));
    }
}

// ---------------- GEMM common geometry ---------------------------------------
#define G_SS 20
#define G_SA_WORDS (128 * G_SS)      // 2560 words per stage
#define G_SB_WORDS (64 * G_SS)       // 1280 words per stage

// ---------------- kernel 4: GEMM1 (128 threads, 64x32 warp tiles) -----------
// Block tile 128x64, BK=32 halves, 3-stage cp.async. 4 warps, each 64x32.
__global__ void __launch_bounds__(128) gemm_qkv_tc() {
    __shared__ __align__(16) uint32_t sh[3 * G_SA_WORDS + 3 * G_SB_WORDS];  // 45 KB
    uint32_t* sAb = sh;
    uint32_t sA_s = (uint32_t)__cvta_generic_to_shared(sAb);
    uint32_t sB_s = sA_s + 3 * G_SA_WORDS * 4;

    int m0 = blockIdx.y * 128;
    int n0 = blockIdx.x * 64;
    int t = threadIdx.x;
    int lane = t & 31, warp = t >> 5;
    int wm = (warp >> 1) << 6;       // 0,64
    int wn = (warp & 1) << 5;        // 0,32
    int lr = lane >> 2, lc = lane & 3;

    // cp.async chunk mapping: chunk c -> row = c>>2, h = (c&3)*8
    // A: 512 chunks (4/thread); B: 256 chunks (2/thread)
    // ldmatrix base addresses
    uint32_t aAddr = sA_s + (((wm + (lane & 15)) * G_SS + ((lane >> 4) << 2)) << 2);
    // B paired LDSM4: groups of 8 lanes -> (j, kb), (j+8rows, kb), (j, kb+4), (j+8, kb+4)
    uint32_t bAddr = sB_s + (((wn + (lane & 7) + (((lane >> 3) & 1) << 3)) * G_SS
                              + ((lane >> 4) << 2)) << 2);

    float c[4][4][4];
#pragma unroll
    for (int i = 0; i < 4; i++)
#pragma unroll
        for (int j = 0; j < 4; j++)
#pragma unroll
            for (int q = 0; q < 4; q++) c[i][j][q] = 0.f;

#define G1L(stg, k0) do {                                                          \
        uint32_t dA = sA_s + ((stg) * G_SA_WORDS) * 4;                             \
        _Pragma("unroll")                                                          \
        for (int r = 0; r < 4; r++) {                                              \
            int cidx = t + r * 128;                                                \
            int am = cidx >> 2, ah = (cidx & 3) << 3;                              \
            cp16(dA + (am * G_SS + (ah >> 1)) * 4,                                 \
                 d_xh + (size_t)(m0 + am) * CIN + (k0) + ah);                      \
        }                                                                          \
        uint32_t dB = sB_s + ((stg) * G_SB_WORDS) * 4;                             \
        _Pragma("unroll")                                                          \
        for (int r = 0; r < 2; r++) {                                              \
            int cidx = t + r * 128;                                                \
            int bn = cidx >> 2, bh = (cidx & 3) << 3;                              \
            cp16(dB + (bn * G_SS + (bh >> 1)) * 4,                                 \
                 d_wfh + (size_t)(n0 + bn) * CIN + (k0) + bh);                     \
        }                                                                          \
    } while (0)

    G1L(0, 0);  CP_COMMIT();
    G1L(1, 32); CP_COMMIT();

    for (int it = 0; it < 6; it++) {
        CP_WAIT1();
        __syncthreads();
        int k0n = (it + 2) * 32;
        if (k0n < CIN) { G1L((it + 2) % 3, k0n); }
        CP_COMMIT();
        uint32_t aSt = aAddr + (it % 3) * (G_SA_WORDS * 4);
        uint32_t bSt = bAddr + (it % 3) * (G_SB_WORDS * 4);
#pragma unroll
        for (int ks = 0; ks < 2; ks++) {
            int kbb = ks * 32;
            uint32_t a[4][4], bfr[4][2];
#pragma unroll
            for (int i = 0; i < 4; i++)
                LDSM4(a[i], aSt + i * (16 * G_SS * 4) + kbb);
#pragma unroll
            for (int j2 = 0; j2 < 2; j2++) {
                uint32_t r[4];
                LDSM4(r, bSt + j2 * (16 * G_SS * 4) + kbb);
                bfr[j2 * 2 + 0][0] = r[0]; bfr[j2 * 2 + 0][1] = r[2];
                bfr[j2 * 2 + 1][0] = r[1]; bfr[j2 * 2 + 1][1] = r[3];
            }
#pragma unroll
            for (int i = 0; i < 4; i++)
#pragma unroll
                for (int j = 0; j < 4; j++)
                    mma_f16(c[i][j], a[i], bfr[j]);
        }
    }

#pragma unroll
    for (int i = 0; i < 4; i++) {
        int row0 = m0 + wm + i * 16 + lr;
#pragma unroll
        for (int j = 0; j < 4; j++) {
            int col = n0 + wn + j * 8 + (lc << 1);
            float b0 = d_bfused[col], b1 = d_bfused[col + 1];
            *(uint32_t*)&d_qkv[(size_t)row0 * NQKV + col] = pack2(c[i][j][0] + b0, c[i][j][1] + b1);
            *(uint32_t*)&d_qkv[(size_t)(row0 + 8) * NQKV + col] = pack2(c[i][j][2] + b0, c[i][j][3] + b1);
        }
    }
}

// ---------------- kernel 5: attention (fp16 mma, f32x2 conv) — R12 exact -----
#define AT_KC   2176
#define AT_PNM  0
#define AT_VDM  4352
#define AT_VMD  5504
#define AT_OND  6784
#define AT_RMX  8064
#define AT_RSM  8192
#define AT_TOT  8320
__global__ void __launch_bounds__(256) attn_tc_kernel() {
    __shared__ __align__(16) float sh[AT_TOT];
    float2* qc2 = (float2*)sh;                           // [n][17 f2]
    float2* kc2 = (float2*)(sh + AT_KC);
    uint32_t* pnm16 = (uint32_t*)(sh + AT_PNM);          // [n][36 words]
    uint32_t* vdm16 = (uint32_t*)(sh + AT_VDM);          // [d][36 words]
    unsigned short* vdm16h = (unsigned short*)vdm16;     // [d][72 halves]
    uint32_t* vmd16 = (uint32_t*)(sh + AT_VMD);          // [m][20 words]
    uint32_t* ond16 = (uint32_t*)(sh + AT_OND);          // [n][20 words]
    float* rmaxP = sh + AT_RMX;
    float* rsumP = sh + AT_RSM;

    int w_   = blockIdx.x;
    int head = blockIdx.y;
    int t = threadIdx.x;

    int b   = w_ >> 8;
    int rem = w_ & 255;
    int wi  = rem >> 4, wj = rem & 15;
    int base_pix = b * HW + wi * 8 * WIMG + wj * 8;
    int chq = head * HD;

    // ---- phase 1: load q,k,v (fp16 global) ----
#pragma unroll
    for (int r = 0; r < 2; r++) {
        int idx = t + r * 256;             // 0..511
        int n  = idx >> 3;
        int dq = (idx & 7) << 2;           // 0,4,...,28
        int m = base_pix + ((n >> 3) * WIMG) + (n & 7);
        const unsigned short* p = d_qkv + (size_t)m * NQKV + chq + dq;
        uint2 qraw = *(const uint2*)p;
        uint2 kraw = *(const uint2*)(p + CIN);
        uint2 vraw = *(const uint2*)(p + 2 * CIN);
        float2 q01 = __half22float2(*reinterpret_cast<__half2*>(&qraw.x));
        float2 q23 = __half22float2(*reinterpret_cast<__half2*>(&qraw.y));
        float2 k01 = __half22float2(*reinterpret_cast<__half2*>(&kraw.x));
        float2 k23 = __half22float2(*reinterpret_cast<__half2*>(&kraw.y));
        int dp0 = dq >> 1;                 // d-pair index (even)
        qc2[n * 17 + dp0]     = make_float2(q01.x * SCALE, q01.y * SCALE);
        qc2[n * 17 + dp0 + 1] = make_float2(q23.x * SCALE, q23.y * SCALE);
        kc2[n * 17 + dp0]     = make_float2(k01.x, k01.y);
        kc2[n * 17 + dp0 + 1] = make_float2(k23.x, k23.y);
        const unsigned short* vh = (const unsigned short*)&vraw;
        vdm16h[(dq + 0) * 72 + n] = vh[0];
        vdm16h[(dq + 1) * 72 + n] = vh[1];
        vdm16h[(dq + 2) * 72 + n] = vh[2];
        vdm16h[(dq + 3) * 72 + n] = vh[3];
        vmd16[n * 20 + (dq >> 1)]     = vraw.x;
        vmd16[n * 20 + (dq >> 1) + 1] = vraw.y;
    }
    __syncthreads();

    // ---- phase 2: 8x8 circular conv, packed f32x2 (2 channels/thread) ------
    if (t < 128) {
        int dp = t & 15;
        int ci = t >> 4;
        const unsigned long long* qc = (const unsigned long long*)sh;
        const unsigned long long* kc = (const unsigned long long*)(sh + AT_KC);
        unsigned long long acc[8];
#pragma unroll
        for (int j = 0; j < 8; j++) acc[j] = 0ull;
#pragma unroll
        for (int ai = 0; ai < 8; ai++) {
            int ki = (ci - ai) & 7;
            unsigned long long qr[8], kr[8];
#pragma unroll
            for (int e = 0; e < 8; e++) qr[e] = qc[(ai * 8 + e) * 17 + dp];
#pragma unroll
            for (int e = 0; e < 8; e++) kr[e] = kc[(ki * 8 + e) * 17 + dp];
#pragma unroll
            for (int aj = 0; aj < 8; aj++)
#pragma unroll
                for (int j = 0; j < 8; j++)
                    fma2(acc[j], qr[aj], kr[(j - aj) & 7]);
        }
#pragma unroll
        for (int j = 0; j < 8; j++) {
            float fx, fy;
            asm("mov.b64 {%0, %1}, %2;" : "=f"(fx), "=f"(fy) : "l"(acc[j]));
            ond16[(ci * 8 + j) * 20 + dp] = pack2(fx, fy);
        }
    }
    __syncthreads();

    // ---- phase 3: logits s = o @ v^T + bias (fp16 mma, K=32 = 2 ksteps) ----
    int lane = t & 31, w = t >> 5;
    int wr = w >> 1, wc = w & 1;      // 4x2 warp grid
    int n0w = wr * 16;
    int lr = lane >> 2, lc = lane & 3;

    uint32_t afr[2][4];
#pragma unroll
    for (int ksv = 0; ksv < 2; ksv++) {
        int kb = ksv * 8;
        afr[ksv][0] = ond16[(n0w + lr) * 20 + kb + lc];
        afr[ksv][1] = ond16[(n0w + lr + 8) * 20 + kb + lc];
        afr[ksv][2] = ond16[(n0w + lr) * 20 + kb + lc + 4];
        afr[ksv][3] = ond16[(n0w + lr + 8) * 20 + kb + lc + 4];
    }
    int m0w = wc * 32;
    float sacc[4][4];
#pragma unroll
    for (int mt = 0; mt < 4; mt++)
#pragma unroll
        for (int q = 0; q < 4; q++) sacc[mt][q] = 0.f;
#pragma unroll
    for (int mt = 0; mt < 4; mt++) {
        int mrow = m0w + mt * 8 + lr;
#pragma unroll
        for (int ksv = 0; ksv < 2; ksv++) {
            int kb = ksv * 8;
            uint32_t bf[2] = {vmd16[mrow * 20 + kb + lc], vmd16[mrow * 20 + kb + lc + 4]};
            mma_f16(sacc[mt], afr[ksv], bf);
        }
    }
    {
        const float* bp = d_biasT + head * NWIN * NWIN;
#pragma unroll
        for (int mt = 0; mt < 4; mt++) {
            int col = m0w + mt * 8 + (lc << 1);
            float2 b0 = *(const float2*)(bp + (n0w + lr) * NWIN + col);
            float2 b1 = *(const float2*)(bp + (n0w + lr + 8) * NWIN + col);
            sacc[mt][0] += b0.x; sacc[mt][1] += b0.y;
            sacc[mt][2] += b1.x; sacc[mt][3] += b1.y;
        }
    }
    float mx0 = -1e30f, mx1 = -1e30f;
#pragma unroll
    for (int mt = 0; mt < 4; mt++) {
        mx0 = fmaxf(mx0, fmaxf(sacc[mt][0], sacc[mt][1]));
        mx1 = fmaxf(mx1, fmaxf(sacc[mt][2], sacc[mt][3]));
    }
    mx0 = fmaxf(mx0, __shfl_xor_sync(0xffffffffu, mx0, 1));
    mx0 = fmaxf(mx0, __shfl_xor_sync(0xffffffffu, mx0, 2));
    mx1 = fmaxf(mx1, __shfl_xor_sync(0xffffffffu, mx1, 1));
    mx1 = fmaxf(mx1, __shfl_xor_sync(0xffffffffu, mx1, 2));
    if (lc == 0) {
        rmaxP[(n0w + lr) * 2 + wc]     = mx0;
        rmaxP[(n0w + lr + 8) * 2 + wc] = mx1;
    }
    __syncthreads();
    float g0 = fmaxf(rmaxP[(n0w + lr) * 2],     rmaxP[(n0w + lr) * 2 + 1]);
    float g1 = fmaxf(rmaxP[(n0w + lr + 8) * 2], rmaxP[(n0w + lr + 8) * 2 + 1]);
    float s0 = 0.f, s1 = 0.f;
#pragma unroll
    for (int mt = 0; mt < 4; mt++) {
        float e0 = __expf(sacc[mt][0] - g0);
        float e1 = __expf(sacc[mt][1] - g0);
        float e2 = __expf(sacc[mt][2] - g1);
        float e3 = __expf(sacc[mt][3] - g1);
        s0 += e0 + e1; s1 += e2 + e3;
        int colw = wc * 16 + mt * 4 + lc;   // word index of m-pair
        pnm16[(n0w + lr) * 36 + colw]     = pack2(e0, e1);
        pnm16[(n0w + lr + 8) * 36 + colw] = pack2(e2, e3);
    }
    s0 += __shfl_xor_sync(0xffffffffu, s0, 1);
    s0 += __shfl_xor_sync(0xffffffffu, s0, 2);
    s1 += __shfl_xor_sync(0xffffffffu, s1, 1);
    s1 += __shfl_xor_sync(0xffffffffu, s1, 2);
    if (lc == 0) {
        rsumP[(n0w + lr) * 2 + wc]     = s0;
        rsumP[(n0w + lr + 8) * 2 + wc] = s1;
    }
    __syncthreads();

    // ---- phase 5: y = p @ v (fp16 mma, K=64 = 4 ksteps), normalize, store ---
    int d0w = wc * 16;
    float yacc[2][4];
#pragma unroll
    for (int dt = 0; dt < 2; dt++)
#pragma unroll
        for (int q = 0; q < 4; q++) yacc[dt][q] = 0.f;
#pragma unroll
    for (int st = 0; st < 4; st++) {
        int kb = st * 8;
        uint32_t a[4] = {
            pnm16[(n0w + lr) * 36 + kb + lc],
            pnm16[(n0w + lr + 8) * 36 + kb + lc],
            pnm16[(n0w + lr) * 36 + kb + lc + 4],
            pnm16[(n0w + lr + 8) * 36 + kb + lc + 4]};
#pragma unroll
        for (int dt = 0; dt < 2; dt++) {
            int dcol = d0w + dt * 8 + lr;
            uint32_t bf[2] = {vdm16[dcol * 36 + kb + lc], vdm16[dcol * 36 + kb + lc + 4]};
            mma_f16(yacc[dt], a, bf);
        }
    }
    {
        int r0 = n0w + lr, r1 = r0 + 8;
        float ri0 = 1.f / (rsumP[2 * r0] + rsumP[2 * r0 + 1]);
        float ri1 = 1.f / (rsumP[2 * r1] + rsumP[2 * r1 + 1]);
        int p0 = base_pix + ((r0 >> 3) * WIMG) + (r0 & 7);
        int p1 = base_pix + ((r1 >> 3) * WIMG) + (r1 & 7);
#pragma unroll
        for (int dt = 0; dt < 2; dt++) {
            int dc = chq + d0w + dt * 8 + (lc << 1);
            *(uint32_t*)&d_yb[(size_t)p0 * CIN + dc] = pack2(yacc[dt][0] * ri0, yacc[dt][1] * ri0);
            *(uint32_t*)&d_yb[(size_t)p1 * CIN + dc] = pack2(yacc[dt][2] * ri1, yacc[dt][3] * ri1);
        }
    }
}

// ---------------- kernel 6: GEMM2 out = yb @ pwh^T + pb ---------------------
__global__ void __launch_bounds__(256) gemm_proj_tc(const float* __restrict__ pb,
                                                    float* __restrict__ out) {
    __shared__ __align__(16) uint32_t sh[3 * G_SA_WORDS + 3 * G_SB_WORDS];  // 45 KB
    uint32_t* sAb = sh;
    uint32_t* sBb = sh + 3 * G_SA_WORDS;
    uint32_t sA_s = (uint32_t)__cvta_generic_to_shared(sAb);
    uint32_t sB_s = (uint32_t)__cvta_generic_to_shared(sBb);

    int m0 = blockIdx.y * 128;
    int n0 = blockIdx.x * 64;
    int b  = m0 >> 14;
    int hw0 = m0 & (HW - 1);

    int t = threadIdx.x;
    int lane = t & 31, warp = t >> 5;
    int wm = (warp >> 1) << 5, wn = (warp & 1) << 5;
    int lr = lane >> 2, lc = lane & 3;

    int a_m0 = t >> 2,         a_h0 = (t & 3) << 3;
    int a_m1 = (t + 256) >> 2, a_h1 = a_h0;
    int b_n = t >> 2,          b_h = (t & 3) << 3;

    uint32_t aAddr = sA_s + (((wm + (lane & 15)) * G_SS + ((lane >> 4) << 2)) << 2);
    uint32_t bAddr = sB_s + (((wn + (lane & 7)) * G_SS + (((lane >> 3) & 1) << 2)) << 2);

    float c[2][4][4];
#pragma unroll
    for (int i = 0; i < 2; i++)
#pragma unroll
        for (int j = 0; j < 4; j++)
#pragma unroll
            for (int q = 0; q < 4; q++) c[i][j][q] = 0.f;

#define G2L(stg, k0) do {                                                          \
        uint32_t dA = sA_s + ((stg) * G_SA_WORDS) * 4;                             \
        cp16(dA + (a_m0 * G_SS + (a_h0 >> 1)) * 4, d_yb + (size_t)(m0 + a_m0) * CIN + (k0) + a_h0); \
        cp16(dA + (a_m1 * G_SS + (a_h1 >> 1)) * 4, d_yb + (size_t)(m0 + a_m1) * CIN + (k0) + a_h1); \
        uint32_t dB = sB_s + ((stg) * G_SB_WORDS) * 4;                             \
        cp16(dB + (b_n * G_SS + (b_h >> 1)) * 4, d_pwh + (size_t)(n0 + b_n) * CIN + (k0) + b_h); \
    } while (0)

    G2L(0, 0);  CP_COMMIT();
    G2L(1, 32); CP_COMMIT();

    for (int it = 0; it < 6; it++) {
        CP_WAIT1();
        __syncthreads();
        int k0n = (it + 2) * 32;
        if (k0n < CIN) { G2L((it + 2) % 3, k0n); }
        CP_COMMIT();
        uint32_t aSt = aAddr + (it % 3) * (G_SA_WORDS * 4);
        uint32_t bSt = bAddr + (it % 3) * (G_SB_WORDS * 4);
#pragma unroll
        for (int ks = 0; ks < 2; ks++) {
            int kbb = ks * 32;
            uint32_t a[2][4], bfr[4][2];
#pragma unroll
            for (int i = 0; i < 2; i++)
                LDSM4(a[i], aSt + i * (16 * G_SS * 4) + kbb);
#pragma unroll
            for (int j = 0; j < 4; j++)
                LDSM2(bfr[j][0], bfr[j][1], bSt + j * (8 * G_SS * 4) + kbb);
#pragma unroll
            for (int i = 0; i < 2; i++)
#pragma unroll
                for (int j = 0; j < 4; j++)
                    mma_f16(c[i][j], a[i], bfr[j]);
        }
    }
    __syncthreads();

    // stage C in smem for coalesced transposed output
    float* Cs = (float*)sh;   // [128][65]
#pragma unroll
    for (int i = 0; i < 2; i++) {
        int row = wm + i * 16 + lr;
#pragma unroll
        for (int j = 0; j < 4; j++) {
            int col = wn + j * 8 + (lc << 1);
            Cs[row * 65 + col]           = c[i][j][0];
            Cs[row * 65 + col + 1]       = c[i][j][1];
            Cs[(row + 8) * 65 + col]     = c[i][j][2];
            Cs[(row + 8) * 65 + col + 1] = c[i][j][3];
        }
    }
    __syncthreads();

    int mL = t & 127;
    int nh = (t >> 7) << 5;
    for (int nn = 0; nn < 32; nn++) {
        int n = nh + nn;
        out[(size_t)(b * CIN + n0 + n) * HW + hw0 + mL] = Cs[mL * 65 + n] + pb[n0 + n];
    }
}

// ---------------- launch -----------------------------------------------------
extern "C" void kernel_launch(void* const* d_in, const int* in_sizes, int n_in,
                              void* d_out, int out_size) {
    const float* x      = (const float*)d_in[0];
    const float* V_w    = (const float*)d_in[1];
    const float* V_b    = (const float*)d_in[2];
    const float* QK_w   = (const float*)d_in[3];
    const float* QK_b   = (const float*)d_in[4];
    const float* proj_w = (const float*)d_in[5];
    const float* proj_b = (const float*)d_in[6];
    const float* mw1    = (const float*)d_in[7];
    const float* mb1    = (const float*)d_in[8];
    const float* mw2    = (const float*)d_in[9];
    const float* mb2    = (const float*)d_in[10];
    float* out = (float*)d_out;

    prep_w<<<(NQKV * CIN + 255) / 256, 256>>>(QK_w, QK_b, V_w, V_b, proj_w);
    bias_kernel<<<(NWIN * NWIN + 255) / 256, 256>>>(mw1, mb1, mw2, mb2);
    transpose_x<<<dim3(CIN / 32, MTOT / 32), 256>>>(x);
    gemm_qkv_tc<<<dim3(NQKV / 64, MTOT / 128), 128>>>();
    attn_tc_kernel<<<dim3(2048, NH), 256>>>();
    gemm_proj_tc<<<dim3(CIN / 64, MTOT / 128), 256>>>(proj_b, out);
}

// round 17
// speedup vs baseline: 1.0261x; 1.0261x over previous
#include <cuda_runtime.h>
#include <cuda_fp16.h>
#include <math.h>
#include <stdint.h>

// Problem constants
#define BATCH 8
#define CIN   192
#define HIMG  128
#define WIMG  128
#define HW    16384           // 128*128
#define MTOT  131072          // BATCH*HW
#define NQKV  576             // 3*C
#define NH    6
#define HD    32
#define WS    8
#define NWIN  64              // WS*WS
#define SCALE 0.17677669529663687f   // 32^-0.5

// ---------------- scratch (device globals; no runtime allocation) -----------
__device__ __align__(16) unsigned short d_xh [(size_t)MTOT * CIN];   // x^T fp16 [m][c]
__device__ __align__(16) unsigned short d_qkv[(size_t)MTOT * NQKV];  // fp16 [m][576]
__device__ __align__(16) unsigned short d_yb [(size_t)MTOT * CIN];   // fp16 [m][192]
__device__ __align__(16) unsigned short d_wfh[NQKV * CIN];           // fp16 [576][192]
__device__ __align__(16) unsigned short d_pwh[CIN * CIN];            // fp16 [192][192]
__device__ float d_bfused[NQKV];
__device__ float d_biasT[NH * NWIN * NWIN];      // [head][n][m]

// ---------------- helpers ----------------------------------------------------
__device__ __forceinline__ void mma_f16(float c[4], const uint32_t a[4], const uint32_t b[2]) {
    asm volatile(
        "mma.sync.aligned.m16n8k16.row.col.f32.f16.f16.f32 "
        "{%0,%1,%2,%3}, {%4,%5,%6,%7}, {%8,%9}, {%0,%1,%2,%3};"
        : "+f"(c[0]), "+f"(c[1]), "+f"(c[2]), "+f"(c[3])
        : "r"(a[0]), "r"(a[1]), "r"(a[2]), "r"(a[3]), "r"(b[0]), "r"(b[1]));
}
__device__ __forceinline__ uint32_t pack2(float a, float b) {
    __half2 h = __floats2half2_rn(a, b);
    return *reinterpret_cast<uint32_t*>(&h);
}
__device__ __forceinline__ void fma2(unsigned long long& acc, unsigned long long a,
                                     unsigned long long b) {
    asm("fma.rn.f32x2 %0, %1, %2, %0;" : "+l"(acc) : "l"(a), "l"(b));
}
__device__ __forceinline__ void cp16(uint32_t saddr, const void* g) {
    asm volatile("cp.async.cg.shared.global [%0], [%1], 16;" :: "r"(saddr), "l"(g));
}
#define CP_COMMIT() asm volatile("cp.async.commit_group;")
#define CP_WAIT1()  asm volatile("cp.async.wait_group 1;")

#define LDSM4(r, addr) \
    asm volatile("ldmatrix.sync.aligned.m8n8.x4.shared.b16 {%0,%1,%2,%3}, [%4];" \
                 : "=r"((r)[0]), "=r"((r)[1]), "=r"((r)[2]), "=r"((r)[3]) : "r"(addr))
#define LDSM2(r0, r1, addr) \
    asm volatile("ldmatrix.sync.aligned.m8n8.x2.shared.b16 {%0,%1}, [%2];" \
                 : "=r"(r0), "=r"(r1) : "r"(addr))

// ---------------- kernel 1: prep (fuse weights + fp16 convert + bias MLP) ----
__global__ void prep_w(const float* __restrict__ QK_w, const float* __restrict__ QK_b,
                       const float* __restrict__ V_w,  const float* __restrict__ V_b,
                       const float* __restrict__ pw,
                       const float* __restrict__ w1, const float* __restrict__ b1,
                       const float* __restrict__ w2, const float* __restrict__ b2) {
    int idx = blockIdx.x * 256 + threadIdx.x;
    if (idx < NQKV * CIN) {
        int n = idx / CIN, k = idx - n * CIN;
        float v = (n < 2 * CIN) ? QK_w[n * CIN + k] : V_w[(n - 2 * CIN) * CIN + k];
        d_wfh[idx] = __half_as_ushort(__float2half(v));
    }
    if (idx < CIN * CIN)
        d_pwh[idx] = __half_as_ushort(__float2half(pw[idx]));
    if (idx < NQKV)
        d_bfused[idx] = (idx < 2 * CIN) ? QK_b[idx] : V_b[idx - 2 * CIN];
    // relative-position bias via meta MLP (first 4096 threads)
    if (idx < NWIN * NWIN) {
        int n1 = idx >> 6, n2 = idx & 63;
        float di = (float)((n1 >> 3) - (n2 >> 3));
        float dj = (float)((n1 & 7) - (n2 & 7));
        float s0 = (di > 0.f) ? 1.f : ((di < 0.f) ? -1.f : 0.f);
        float s1 = (dj > 0.f) ? 1.f : ((dj < 0.f) ? -1.f : 0.f);
        float rp0 = s0 * log1pf(fabsf(di));
        float rp1 = s1 * log1pf(fabsf(dj));
        float acc[NH];
#pragma unroll
        for (int c = 0; c < NH; c++) acc[c] = b2[c];
        for (int tt = 0; tt < 256; tt++) {
            float h = rp0 * w1[tt] + rp1 * w1[256 + tt] + b1[tt];
            h = fmaxf(h, 0.f);
#pragma unroll
            for (int c = 0; c < NH; c++) acc[c] += h * w2[tt * NH + c];
        }
#pragma unroll
        for (int c = 0; c < NH; c++)
            d_biasT[(c * NWIN + n1) * NWIN + n2] = acc[c];
    }
}

// ---------------- kernel 3: transpose+convert x -> d_xh fp16 [m][c] ---------
// 32x32 tile; stores widened: each thread packs 2 adjacent channels (4B).
__global__ void __launch_bounds__(256) transpose_x(const float* __restrict__ x) {
    __shared__ float tile[32][33];
    int cb = blockIdx.x << 5;
    int mb = blockIdx.y << 5;
    int b  = mb >> 14;
    int hw0 = mb & (HW - 1);
    int tx = threadIdx.x & 31, ty = threadIdx.x >> 5;
    const float* src = x + (size_t)b * CIN * HW + hw0;
#pragma unroll
    for (int i = 0; i < 4; i++)
        tile[ty + i * 8][tx] = src[(size_t)(cb + ty + i * 8) * HW + tx];
    __syncthreads();
#pragma unroll
    for (int it = 0; it < 2; it++) {
        int u = threadIdx.x + it * 256;     // 0..511
        int mLoc = u >> 4;                  // 0..31
        int cp   = u & 15;                  // channel pair
        int m = mb + mLoc;
        float v0 = tile[2 * cp][mLoc];
        float v1 = tile[2 * cp + 1][mLoc];
        *(uint32_t*)&d_xh[(size_t)m * CIN + cb + 2 * cp] = pack2(v0, v1);
    }
}

// ---------------- GEMM common geometry ---------------------------------------
#define G_SS 20
#define G_SA_WORDS (128 * G_SS)      // 2560 words per stage
#define G_SB_WORDS (64 * G_SS)       // 1280 words per stage

// ---------------- kernel 4: GEMM1 qkv = xh @ wfh^T + b (R12 config) ---------
__global__ void __launch_bounds__(256) gemm_qkv_tc() {
    __shared__ __align__(16) uint32_t sh[3 * G_SA_WORDS + 3 * G_SB_WORDS];  // 45 KB
    uint32_t* sAb = sh;
    uint32_t* sBb = sh + 3 * G_SA_WORDS;
    uint32_t sA_s = (uint32_t)__cvta_generic_to_shared(sAb);
    uint32_t sB_s = (uint32_t)__cvta_generic_to_shared(sBb);

    int m0 = blockIdx.y * 128;
    int n0 = blockIdx.x * 64;
    int t = threadIdx.x;
    int lane = t & 31, warp = t >> 5;
    int wm = (warp >> 1) << 5, wn = (warp & 1) << 5;
    int lr = lane >> 2, lc = lane & 3;

    int a_m0 = t >> 2,         a_h0 = (t & 3) << 3;
    int a_m1 = (t + 256) >> 2, a_h1 = a_h0;
    int b_n = t >> 2,          b_h = (t & 3) << 3;

    uint32_t aAddr = sA_s + (((wm + (lane & 15)) * G_SS + ((lane >> 4) << 2)) << 2);
    uint32_t bAddr = sB_s + (((wn + (lane & 7)) * G_SS + (((lane >> 3) & 1) << 2)) << 2);

    float c[2][4][4];
#pragma unroll
    for (int i = 0; i < 2; i++)
#pragma unroll
        for (int j = 0; j < 4; j++)
#pragma unroll
            for (int q = 0; q < 4; q++) c[i][j][q] = 0.f;

#define G1L(stg, k0) do {                                                          \
        uint32_t dA = sA_s + ((stg) * G_SA_WORDS) * 4;                             \
        cp16(dA + (a_m0 * G_SS + (a_h0 >> 1)) * 4, d_xh + (size_t)(m0 + a_m0) * CIN + (k0) + a_h0); \
        cp16(dA + (a_m1 * G_SS + (a_h1 >> 1)) * 4, d_xh + (size_t)(m0 + a_m1) * CIN + (k0) + a_h1); \
        uint32_t dB = sB_s + ((stg) * G_SB_WORDS) * 4;                             \
        cp16(dB + (b_n * G_SS + (b_h >> 1)) * 4, d_wfh + (size_t)(n0 + b_n) * CIN + (k0) + b_h); \
    } while (0)

    G1L(0, 0);  CP_COMMIT();
    G1L(1, 32); CP_COMMIT();

    for (int it = 0; it < 6; it++) {
        CP_WAIT1();
        __syncthreads();
        int k0n = (it + 2) * 32;
        if (k0n < CIN) { G1L((it + 2) % 3, k0n); }
        CP_COMMIT();
        uint32_t aSt = aAddr + (it % 3) * (G_SA_WORDS * 4);
        uint32_t bSt = bAddr + (it % 3) * (G_SB_WORDS * 4);
#pragma unroll
        for (int ks = 0; ks < 2; ks++) {
            int kbb = ks * 32;
            uint32_t a[2][4], bfr[4][2];
#pragma unroll
            for (int i = 0; i < 2; i++)
                LDSM4(a[i], aSt + i * (16 * G_SS * 4) + kbb);
#pragma unroll
            for (int j = 0; j < 4; j++)
                LDSM2(bfr[j][0], bfr[j][1], bSt + j * (8 * G_SS * 4) + kbb);
#pragma unroll
            for (int i = 0; i < 2; i++)
#pragma unroll
                for (int j = 0; j < 4; j++)
                    mma_f16(c[i][j], a[i], bfr[j]);
        }
    }

#pragma unroll
    for (int i = 0; i < 2; i++) {
        int row0 = m0 + wm + i * 16 + lr;
#pragma unroll
        for (int j = 0; j < 4; j++) {
            int col = n0 + wn + j * 8 + (lc << 1);
            float b0 = d_bfused[col], b1 = d_bfused[col + 1];
            *(uint32_t*)&d_qkv[(size_t)row0 * NQKV + col] = pack2(c[i][j][0] + b0, c[i][j][1] + b1);
            *(uint32_t*)&d_qkv[(size_t)(row0 + 8) * NQKV + col] = pack2(c[i][j][2] + b0, c[i][j][3] + b1);
        }
    }
}

// ---------------- kernel 5: attention (fp16 mma, f32x2 conv) — R12 exact -----
#define AT_KC   2176
#define AT_PNM  0
#define AT_VDM  4352
#define AT_VMD  5504
#define AT_OND  6784
#define AT_RMX  8064
#define AT_RSM  8192
#define AT_TOT  8320
__global__ void __launch_bounds__(256) attn_tc_kernel() {
    __shared__ __align__(16) float sh[AT_TOT];
    float2* qc2 = (float2*)sh;                           // [n][17 f2]
    float2* kc2 = (float2*)(sh + AT_KC);
    uint32_t* pnm16 = (uint32_t*)(sh + AT_PNM);          // [n][36 words]
    uint32_t* vdm16 = (uint32_t*)(sh + AT_VDM);          // [d][36 words]
    unsigned short* vdm16h = (unsigned short*)vdm16;     // [d][72 halves]
    uint32_t* vmd16 = (uint32_t*)(sh + AT_VMD);          // [m][20 words]
    uint32_t* ond16 = (uint32_t*)(sh + AT_OND);          // [n][20 words]
    float* rmaxP = sh + AT_RMX;
    float* rsumP = sh + AT_RSM;

    int w_   = blockIdx.x;
    int head = blockIdx.y;
    int t = threadIdx.x;

    int b   = w_ >> 8;
    int rem = w_ & 255;
    int wi  = rem >> 4, wj = rem & 15;
    int base_pix = b * HW + wi * 8 * WIMG + wj * 8;
    int chq = head * HD;

    // ---- phase 1: load q,k,v (fp16 global) ----
#pragma unroll
    for (int r = 0; r < 2; r++) {
        int idx = t + r * 256;             // 0..511
        int n  = idx >> 3;
        int dq = (idx & 7) << 2;           // 0,4,...,28
        int m = base_pix + ((n >> 3) * WIMG) + (n & 7);
        const unsigned short* p = d_qkv + (size_t)m * NQKV + chq + dq;
        uint2 qraw = *(const uint2*)p;
        uint2 kraw = *(const uint2*)(p + CIN);
        uint2 vraw = *(const uint2*)(p + 2 * CIN);
        float2 q01 = __half22float2(*reinterpret_cast<__half2*>(&qraw.x));
        float2 q23 = __half22float2(*reinterpret_cast<__half2*>(&qraw.y));
        float2 k01 = __half22float2(*reinterpret_cast<__half2*>(&kraw.x));
        float2 k23 = __half22float2(*reinterpret_cast<__half2*>(&kraw.y));
        int dp0 = dq >> 1;                 // d-pair index (even)
        qc2[n * 17 + dp0]     = make_float2(q01.x * SCALE, q01.y * SCALE);
        qc2[n * 17 + dp0 + 1] = make_float2(q23.x * SCALE, q23.y * SCALE);
        kc2[n * 17 + dp0]     = make_float2(k01.x, k01.y);
        kc2[n * 17 + dp0 + 1] = make_float2(k23.x, k23.y);
        const unsigned short* vh = (const unsigned short*)&vraw;
        vdm16h[(dq + 0) * 72 + n] = vh[0];
        vdm16h[(dq + 1) * 72 + n] = vh[1];
        vdm16h[(dq + 2) * 72 + n] = vh[2];
        vdm16h[(dq + 3) * 72 + n] = vh[3];
        vmd16[n * 20 + (dq >> 1)]     = vraw.x;
        vmd16[n * 20 + (dq >> 1) + 1] = vraw.y;
    }
    __syncthreads();

    // ---- phase 2: 8x8 circular conv, packed f32x2 (2 channels/thread) ------
    if (t < 128) {
        int dp = t & 15;
        int ci = t >> 4;
        const unsigned long long* qc = (const unsigned long long*)sh;
        const unsigned long long* kc = (const unsigned long long*)(sh + AT_KC);
        unsigned long long acc[8];
#pragma unroll
        for (int j = 0; j < 8; j++) acc[j] = 0ull;
#pragma unroll
        for (int ai = 0; ai < 8; ai++) {
            int ki = (ci - ai) & 7;
            unsigned long long qr[8], kr[8];
#pragma unroll
            for (int e = 0; e < 8; e++) qr[e] = qc[(ai * 8 + e) * 17 + dp];
#pragma unroll
            for (int e = 0; e < 8; e++) kr[e] = kc[(ki * 8 + e) * 17 + dp];
#pragma unroll
            for (int aj = 0; aj < 8; aj++)
#pragma unroll
                for (int j = 0; j < 8; j++)
                    fma2(acc[j], qr[aj], kr[(j - aj) & 7]);
        }
#pragma unroll
        for (int j = 0; j < 8; j++) {
            float fx, fy;
            asm("mov.b64 {%0, %1}, %2;" : "=f"(fx), "=f"(fy) : "l"(acc[j]));
            ond16[(ci * 8 + j) * 20 + dp] = pack2(fx, fy);
        }
    }
    __syncthreads();

    // ---- phase 3: logits s = o @ v^T + bias (fp16 mma, K=32 = 2 ksteps) ----
    int lane = t & 31, w = t >> 5;
    int wr = w >> 1, wc = w & 1;      // 4x2 warp grid
    int n0w = wr * 16;
    int lr = lane >> 2, lc = lane & 3;

    uint32_t afr[2][4];
#pragma unroll
    for (int ksv = 0; ksv < 2; ksv++) {
        int kb = ksv * 8;
        afr[ksv][0] = ond16[(n0w + lr) * 20 + kb + lc];
        afr[ksv][1] = ond16[(n0w + lr + 8) * 20 + kb + lc];
        afr[ksv][2] = ond16[(n0w + lr) * 20 + kb + lc + 4];
        afr[ksv][3] = ond16[(n0w + lr + 8) * 20 + kb + lc + 4];
    }
    int m0w = wc * 32;
    float sacc[4][4];
#pragma unroll
    for (int mt = 0; mt < 4; mt++)
#pragma unroll
        for (int q = 0; q < 4; q++) sacc[mt][q] = 0.f;
#pragma unroll
    for (int mt = 0; mt < 4; mt++) {
        int mrow = m0w + mt * 8 + lr;
#pragma unroll
        for (int ksv = 0; ksv < 2; ksv++) {
            int kb = ksv * 8;
            uint32_t bf[2] = {vmd16[mrow * 20 + kb + lc], vmd16[mrow * 20 + kb + lc + 4]};
            mma_f16(sacc[mt], afr[ksv], bf);
        }
    }
    {
        const float* bp = d_biasT + head * NWIN * NWIN;
#pragma unroll
        for (int mt = 0; mt < 4; mt++) {
            int col = m0w + mt * 8 + (lc << 1);
            float2 b0 = *(const float2*)(bp + (n0w + lr) * NWIN + col);
            float2 b1 = *(const float2*)(bp + (n0w + lr + 8) * NWIN + col);
            sacc[mt][0] += b0.x; sacc[mt][1] += b0.y;
            sacc[mt][2] += b1.x; sacc[mt][3] += b1.y;
        }
    }
    float mx0 = -1e30f, mx1 = -1e30f;
#pragma unroll
    for (int mt = 0; mt < 4; mt++) {
        mx0 = fmaxf(mx0, fmaxf(sacc[mt][0], sacc[mt][1]));
        mx1 = fmaxf(mx1, fmaxf(sacc[mt][2], sacc[mt][3]));
    }
    mx0 = fmaxf(mx0, __shfl_xor_sync(0xffffffffu, mx0, 1));
    mx0 = fmaxf(mx0, __shfl_xor_sync(0xffffffffu, mx0, 2));
    mx1 = fmaxf(mx1, __shfl_xor_sync(0xffffffffu, mx1, 1));
    mx1 = fmaxf(mx1, __shfl_xor_sync(0xffffffffu, mx1, 2));
    if (lc == 0) {
        rmaxP[(n0w + lr) * 2 + wc]     = mx0;
        rmaxP[(n0w + lr + 8) * 2 + wc] = mx1;
    }
    __syncthreads();
    float g0 = fmaxf(rmaxP[(n0w + lr) * 2],     rmaxP[(n0w + lr) * 2 + 1]);
    float g1 = fmaxf(rmaxP[(n0w + lr + 8) * 2], rmaxP[(n0w + lr + 8) * 2 + 1]);
    float s0 = 0.f, s1 = 0.f;
#pragma unroll
    for (int mt = 0; mt < 4; mt++) {
        float e0 = __expf(sacc[mt][0] - g0);
        float e1 = __expf(sacc[mt][1] - g0);
        float e2 = __expf(sacc[mt][2] - g1);
        float e3 = __expf(sacc[mt][3] - g1);
        s0 += e0 + e1; s1 += e2 + e3;
        int colw = wc * 16 + mt * 4 + lc;   // word index of m-pair
        pnm16[(n0w + lr) * 36 + colw]     = pack2(e0, e1);
        pnm16[(n0w + lr + 8) * 36 + colw] = pack2(e2, e3);
    }
    s0 += __shfl_xor_sync(0xffffffffu, s0, 1);
    s0 += __shfl_xor_sync(0xffffffffu, s0, 2);
    s1 += __shfl_xor_sync(0xffffffffu, s1, 1);
    s1 += __shfl_xor_sync(0xffffffffu, s1, 2);
    if (lc == 0) {
        rsumP[(n0w + lr) * 2 + wc]     = s0;
        rsumP[(n0w + lr + 8) * 2 + wc] = s1;
    }
    __syncthreads();

    // ---- phase 5: y = p @ v (fp16 mma, K=64 = 4 ksteps), normalize, store ---
    int d0w = wc * 16;
    float yacc[2][4];
#pragma unroll
    for (int dt = 0; dt < 2; dt++)
#pragma unroll
        for (int q = 0; q < 4; q++) yacc[dt][q] = 0.f;
#pragma unroll
    for (int st = 0; st < 4; st++) {
        int kb = st * 8;
        uint32_t a[4] = {
            pnm16[(n0w + lr) * 36 + kb + lc],
            pnm16[(n0w + lr + 8) * 36 + kb + lc],
            pnm16[(n0w + lr) * 36 + kb + lc + 4],
            pnm16[(n0w + lr + 8) * 36 + kb + lc + 4]};
#pragma unroll
        for (int dt = 0; dt < 2; dt++) {
            int dcol = d0w + dt * 8 + lr;
            uint32_t bf[2] = {vdm16[dcol * 36 + kb + lc], vdm16[dcol * 36 + kb + lc + 4]};
            mma_f16(yacc[dt], a, bf);
        }
    }
    {
        int r0 = n0w + lr, r1 = r0 + 8;
        float ri0 = 1.f / (rsumP[2 * r0] + rsumP[2 * r0 + 1]);
        float ri1 = 1.f / (rsumP[2 * r1] + rsumP[2 * r1 + 1]);
        int p0 = base_pix + ((r0 >> 3) * WIMG) + (r0 & 7);
        int p1 = base_pix + ((r1 >> 3) * WIMG) + (r1 & 7);
#pragma unroll
        for (int dt = 0; dt < 2; dt++) {
            int dc = chq + d0w + dt * 8 + (lc << 1);
            *(uint32_t*)&d_yb[(size_t)p0 * CIN + dc] = pack2(yacc[dt][0] * ri0, yacc[dt][1] * ri0);
            *(uint32_t*)&d_yb[(size_t)p1 * CIN + dc] = pack2(yacc[dt][2] * ri1, yacc[dt][3] * ri1);
        }
    }
}

// ---------------- kernel 6: GEMM2 out = yb @ pwh^T + pb ---------------------
__global__ void __launch_bounds__(256) gemm_proj_tc(const float* __restrict__ pb,
                                                    float* __restrict__ out) {
    __shared__ __align__(16) uint32_t sh[3 * G_SA_WORDS + 3 * G_SB_WORDS];  // 45 KB
    uint32_t* sAb = sh;
    uint32_t* sBb = sh + 3 * G_SA_WORDS;
    uint32_t sA_s = (uint32_t)__cvta_generic_to_shared(sAb);
    uint32_t sB_s = (uint32_t)__cvta_generic_to_shared(sBb);

    int m0 = blockIdx.y * 128;
    int n0 = blockIdx.x * 64;
    int b  = m0 >> 14;
    int hw0 = m0 & (HW - 1);

    int t = threadIdx.x;
    int lane = t & 31, warp = t >> 5;
    int wm = (warp >> 1) << 5, wn = (warp & 1) << 5;
    int lr = lane >> 2, lc = lane & 3;

    int a_m0 = t >> 2,         a_h0 = (t & 3) << 3;
    int a_m1 = (t + 256) >> 2, a_h1 = a_h0;
    int b_n = t >> 2,          b_h = (t & 3) << 3;

    uint32_t aAddr = sA_s + (((wm + (lane & 15)) * G_SS + ((lane >> 4) << 2)) << 2);
    uint32_t bAddr = sB_s + (((wn + (lane & 7)) * G_SS + (((lane >> 3) & 1) << 2)) << 2);

    float c[2][4][4];
#pragma unroll
    for (int i = 0; i < 2; i++)
#pragma unroll
        for (int j = 0; j < 4; j++)
#pragma unroll
            for (int q = 0; q < 4; q++) c[i][j][q] = 0.f;

#define G2L(stg, k0) do {                                                          \
        uint32_t dA = sA_s + ((stg) * G_SA_WORDS) * 4;                             \
        cp16(dA + (a_m0 * G_SS + (a_h0 >> 1)) * 4, d_yb + (size_t)(m0 + a_m0) * CIN + (k0) + a_h0); \
        cp16(dA + (a_m1 * G_SS + (a_h1 >> 1)) * 4, d_yb + (size_t)(m0 + a_m1) * CIN + (k0) + a_h1); \
        uint32_t dB = sB_s + ((stg) * G_SB_WORDS) * 4;                             \
        cp16(dB + (b_n * G_SS + (b_h >> 1)) * 4, d_pwh + (size_t)(n0 + b_n) * CIN + (k0) + b_h); \
    } while (0)

    G2L(0, 0);  CP_COMMIT();
    G2L(1, 32); CP_COMMIT();

    for (int it = 0; it < 6; it++) {
        CP_WAIT1();
        __syncthreads();
        int k0n = (it + 2) * 32;
        if (k0n < CIN) { G2L((it + 2) % 3, k0n); }
        CP_COMMIT();
        uint32_t aSt = aAddr + (it % 3) * (G_SA_WORDS * 4);
        uint32_t bSt = bAddr + (it % 3) * (G_SB_WORDS * 4);
#pragma unroll
        for (int ks = 0; ks < 2; ks++) {
            int kbb = ks * 32;
            uint32_t a[2][4], bfr[4][2];
#pragma unroll
            for (int i = 0; i < 2; i++)
                LDSM4(a[i], aSt + i * (16 * G_SS * 4) + kbb);
#pragma unroll
            for (int j = 0; j < 4; j++)
                LDSM2(bfr[j][0], bfr[j][1], bSt + j * (8 * G_SS * 4) + kbb);
#pragma unroll
            for (int i = 0; i < 2; i++)
#pragma unroll
                for (int j = 0; j < 4; j++)
                    mma_f16(c[i][j], a[i], bfr[j]);
        }
    }
    __syncthreads();

    // stage C in smem for coalesced transposed output
    float* Cs = (float*)sh;   // [128][65]
#pragma unroll
    for (int i = 0; i < 2; i++) {
        int row = wm + i * 16 + lr;
#pragma unroll
        for (int j = 0; j < 4; j++) {
            int col = wn + j * 8 + (lc << 1);
            Cs[row * 65 + col]           = c[i][j][0];
            Cs[row * 65 + col + 1]       = c[i][j][1];
            Cs[(row + 8) * 65 + col]     = c[i][j][2];
            Cs[(row + 8) * 65 + col + 1] = c[i][j][3];
        }
    }
    __syncthreads();

    int mL = t & 127;
    int nh = (t >> 7) << 5;
    for (int nn = 0; nn < 32; nn++) {
        int n = nh + nn;
        out[(size_t)(b * CIN + n0 + n) * HW + hw0 + mL] = Cs[mL * 65 + n] + pb[n0 + n];
    }
}

// ---------------- launch -----------------------------------------------------
extern "C" void kernel_launch(void* const* d_in, const int* in_sizes, int n_in,
                              void* d_out, int out_size) {
    const float* x      = (const float*)d_in[0];
    const float* V_w    = (const float*)d_in[1];
    const float* V_b    = (const float*)d_in[2];
    const float* QK_w   = (const float*)d_in[3];
    const float* QK_b   = (const float*)d_in[4];
    const float* proj_w = (const float*)d_in[5];
    const float* proj_b = (const float*)d_in[6];
    const float* mw1    = (const float*)d_in[7];
    const float* mb1    = (const float*)d_in[8];
    const float* mw2    = (const float*)d_in[9];
    const float* mb2    = (const float*)d_in[10];
    float* out = (float*)d_out;

    prep_w<<<(NQKV * CIN + 255) / 256, 256>>>(QK_w, QK_b, V_w, V_b, proj_w,
                                              mw1, mb1, mw2, mb2);
    transpose_x<<<dim3(CIN / 32, MTOT / 32), 256>>>(x);
    gemm_qkv_tc<<<dim3(NQKV / 64, MTOT / 128), 256>>>();
    attn_tc_kernel<<<dim3(2048, NH), 256>>>();
    gemm_proj_tc<<<dim3(CIN / 64, MTOT / 128), 256>>>(proj_b, out);
}